// round 3
// baseline (speedup 1.0000x reference)
#include <cuda_runtime.h>
#include <cstdint>

// Problem constants
#define NBUCKETS 16
#define EMBD     1024
#define VOCAB    32000
#define SEQLEN   2048
#define RANK     8
#define BATCH    2
#define NTOK     (BATCH * SEQLEN)          // 4096 tokens
#define BUCKET_SHIFT 7                      // SEQLEN / NBUCKETS = 128 = 1<<7

// Scratch for the low-rank projection (alpha folded in): [NTOK][RANK]
__device__ float g_low[NTOK * RANK];

// ---------------------------------------------------------------------------
// Kernel 1: low[bt][r] = alpha * sum_e hidden[bt][e] * A[bucket(t)][e][r]
// One CTA per token, 256 threads, each thread handles 4 contiguous e.
// ---------------------------------------------------------------------------
__global__ __launch_bounds__(256, 8)
void lowproj_kernel(const float* __restrict__ hidden,
                    const float* __restrict__ A,
                    const float* __restrict__ alpha_p)
{
    const int bt = blockIdx.x;               // 0..4095
    const int t  = bt & (SEQLEN - 1);
    const int bucket = t >> BUCKET_SHIFT;    // t/128, t<2048 so already <16

    const float* __restrict__ h  = hidden + (size_t)bt * EMBD;
    const float* __restrict__ Ab = A + (size_t)bucket * EMBD * RANK;

    const int tid = threadIdx.x;
    const int e0  = tid * 4;

    float acc[RANK];
#pragma unroll
    for (int r = 0; r < RANK; r++) acc[r] = 0.0f;

    const float4 hv = *reinterpret_cast<const float4*>(h + e0);
    const float hj[4] = {hv.x, hv.y, hv.z, hv.w};

#pragma unroll
    for (int j = 0; j < 4; j++) {
        const float4* ar = reinterpret_cast<const float4*>(Ab + (size_t)(e0 + j) * RANK);
        float4 a0 = ar[0];
        float4 a1 = ar[1];
        acc[0] = fmaf(hj[j], a0.x, acc[0]);
        acc[1] = fmaf(hj[j], a0.y, acc[1]);
        acc[2] = fmaf(hj[j], a0.z, acc[2]);
        acc[3] = fmaf(hj[j], a0.w, acc[3]);
        acc[4] = fmaf(hj[j], a1.x, acc[4]);
        acc[5] = fmaf(hj[j], a1.y, acc[5]);
        acc[6] = fmaf(hj[j], a1.z, acc[6]);
        acc[7] = fmaf(hj[j], a1.w, acc[7]);
    }

    // warp reduce
#pragma unroll
    for (int off = 16; off > 0; off >>= 1) {
#pragma unroll
        for (int r = 0; r < RANK; r++)
            acc[r] += __shfl_down_sync(0xFFFFFFFFu, acc[r], off);
    }

    __shared__ float s[8][RANK];   // 8 warps
    const int wid  = tid >> 5;
    const int lane = tid & 31;
    if (lane == 0) {
#pragma unroll
        for (int r = 0; r < RANK; r++) s[wid][r] = acc[r];
    }
    __syncthreads();

    if (tid < RANK) {
        float v = 0.0f;
#pragma unroll
        for (int w = 0; w < 8; w++) v += s[w][tid];
        g_low[bt * RANK + tid] = v * alpha_p[0];
    }
}

// ---------------------------------------------------------------------------
// Kernel 2: out[bt][v] = sum_r low[bt][r] * B[r][v]
// Each thread owns 4 consecutive vocab cols (B panel in registers),
// iterates over a 64-token tile. Streaming float4 stores.
// ---------------------------------------------------------------------------
#define T_TILE 64
#define K2_THREADS 256
#define V4 (VOCAB / 4)        // 8000 float4 per row

__global__ __launch_bounds__(K2_THREADS, 4)
void vocabproj_kernel(const float* __restrict__ B,
                      float* __restrict__ out)
{
    const int v4  = blockIdx.x * K2_THREADS + threadIdx.x;  // float4 column index
    const bool valid = (v4 < V4);
    const int v = v4 * 4;

    // Load B panel into registers: 8 rows x 4 cols
    float4 b[RANK];
#pragma unroll
    for (int r = 0; r < RANK; r++) {
        if (valid)
            b[r] = *reinterpret_cast<const float4*>(B + (size_t)r * VOCAB + v);
        else
            b[r] = make_float4(0.f, 0.f, 0.f, 0.f);
    }

    // Cooperative load of this block's token-tile of low into shared
    __shared__ float slow[T_TILE * RANK];    // 2 KB
    const int tok0 = blockIdx.y * T_TILE;
    for (int i = threadIdx.x; i < T_TILE * RANK / 4; i += K2_THREADS) {
        reinterpret_cast<float4*>(slow)[i] =
            reinterpret_cast<const float4*>(g_low + (size_t)tok0 * RANK)[i];
    }
    __syncthreads();

    if (!valid) return;

    float* __restrict__ op = out + (size_t)tok0 * VOCAB + v;

#pragma unroll 4
    for (int tt = 0; tt < T_TILE; tt++) {
        const float* l = slow + tt * RANK;   // broadcast shared reads
        float4 o;
        o.x = l[0] * b[0].x; o.y = l[0] * b[0].y; o.z = l[0] * b[0].z; o.w = l[0] * b[0].w;
#pragma unroll
        for (int r = 1; r < RANK; r++) {
            o.x = fmaf(l[r], b[r].x, o.x);
            o.y = fmaf(l[r], b[r].y, o.y);
            o.z = fmaf(l[r], b[r].z, o.z);
            o.w = fmaf(l[r], b[r].w, o.w);
        }
        __stcs(reinterpret_cast<float4*>(op), o);   // streaming store, skip L2 retention
        op += VOCAB;
    }
}

// ---------------------------------------------------------------------------
// Launch
// ---------------------------------------------------------------------------
extern "C" void kernel_launch(void* const* d_in, const int* in_sizes, int n_in,
                              void* d_out, int out_size)
{
    const float* hidden = (const float*)d_in[0];   // [2,2048,1024]
    const float* A      = (const float*)d_in[1];   // [16,1024,8]
    const float* B      = (const float*)d_in[2];   // [8,32000]
    const float* alpha  = (const float*)d_in[3];   // scalar
    float* out          = (float*)d_out;           // [2,2048,32000]

    lowproj_kernel<<<NTOK, 256>>>(hidden, A, alpha);

    dim3 grid2((V4 + K2_THREADS - 1) / K2_THREADS,   // 32
               NTOK / T_TILE);                       // 64
    vocabproj_kernel<<<grid2, K2_THREADS>>>(B, out);
}

// round 4
// speedup vs baseline: 1.0658x; 1.0658x over previous
#include <cuda_runtime.h>
#include <cstdint>

// Problem constants
#define NBUCKETS 16
#define EMBD     1024
#define VOCAB    32000
#define SEQLEN   2048
#define RANK     8
#define BATCH    2
#define NTOK     (BATCH * SEQLEN)          // 4096 tokens
#define BUCKET_SHIFT 7                      // SEQLEN / NBUCKETS = 128 = 1<<7

// Scratch for the low-rank projection (alpha folded in): [NTOK][RANK]
__device__ float g_low[NTOK * RANK];

// ---------------------------------------------------------------------------
// Kernel 1 (v2): low[bt][r] = alpha * sum_e hidden[bt][e] * A[bucket(t)][e][r]
//
// 64 CTAs x 64 tokens. Each 64-token tile lies within ONE bucket and ONE
// batch row (64 | 128 | 2048). The A-bucket (32 KB) is loaded ONCE per CTA
// into shared, transposed to sAT[r][e] so the inner loop does conflict-free
// LDS.128 reads. One warp per token, lanes split E, coalesced float4 hidden
// loads, butterfly reduce.
// ---------------------------------------------------------------------------
#define K1_TOKS 64
#define K1_TPB  256

__global__ __launch_bounds__(K1_TPB, 2)
void lowproj_kernel(const float* __restrict__ hidden,
                    const float* __restrict__ A,
                    const float* __restrict__ alpha_p)
{
    __shared__ float sAT[RANK][EMBD];   // 32 KB, transposed A bucket

    const int tok0   = blockIdx.x * K1_TOKS;
    const int bucket = (tok0 & (SEQLEN - 1)) >> BUCKET_SHIFT;
    const float* __restrict__ Ab = A + (size_t)bucket * EMBD * RANK;

    // Cooperative load + transpose: 8192 floats = 2048 float4, 8 per thread.
    // Global float4 i covers (e = i>>1, r = (i&1)*4 .. +3).
    for (int i = threadIdx.x; i < EMBD * RANK / 4; i += K1_TPB) {
        float4 v = reinterpret_cast<const float4*>(Ab)[i];
        const int e = i >> 1;
        const int q = (i & 1) * 4;
        sAT[q + 0][e] = v.x;
        sAT[q + 1][e] = v.y;
        sAT[q + 2][e] = v.z;
        sAT[q + 3][e] = v.w;
    }
    __syncthreads();

    const float alpha = alpha_p[0];
    const int wid  = threadIdx.x >> 5;
    const int lane = threadIdx.x & 31;

    // 8 warps x 8 tokens = 64 tokens
#pragma unroll 1
    for (int ti = 0; ti < K1_TOKS / 8; ti++) {
        const int tok = tok0 + wid * (K1_TOKS / 8) + ti;
        const float* __restrict__ h = hidden + (size_t)tok * EMBD;

        float acc[RANK];
#pragma unroll
        for (int r = 0; r < RANK; r++) acc[r] = 0.0f;

        // lane handles e = lane*4 + k*128, k = 0..7  (1024 total)
#pragma unroll
        for (int k = 0; k < EMBD / 128; k++) {
            const int e = lane * 4 + k * 128;
            const float4 hv = *reinterpret_cast<const float4*>(h + e);
#pragma unroll
            for (int r = 0; r < RANK; r++) {
                const float4 av = *reinterpret_cast<const float4*>(&sAT[r][e]);
                acc[r] = fmaf(hv.x, av.x,
                         fmaf(hv.y, av.y,
                         fmaf(hv.z, av.z,
                         fmaf(hv.w, av.w, acc[r]))));
            }
        }

        // full butterfly so every lane ends with all 8 sums
#pragma unroll
        for (int off = 16; off > 0; off >>= 1) {
#pragma unroll
            for (int r = 0; r < RANK; r++)
                acc[r] += __shfl_xor_sync(0xFFFFFFFFu, acc[r], off);
        }

        if (lane < RANK)
            g_low[tok * RANK + lane] = acc[lane] * alpha;
    }
}

// ---------------------------------------------------------------------------
// Kernel 2: out[bt][v] = sum_r low[bt][r] * B[r][v]
// (unchanged — measured at ~6.85 TB/s store bandwidth, at the HBM/LTS cap)
// ---------------------------------------------------------------------------
#define T_TILE 64
#define K2_THREADS 256
#define V4 (VOCAB / 4)        // 8000 float4 per row

__global__ __launch_bounds__(K2_THREADS, 4)
void vocabproj_kernel(const float* __restrict__ B,
                      float* __restrict__ out)
{
    const int v4  = blockIdx.x * K2_THREADS + threadIdx.x;  // float4 column index
    const bool valid = (v4 < V4);
    const int v = v4 * 4;

    // Load B panel into registers: 8 rows x 4 cols
    float4 b[RANK];
#pragma unroll
    for (int r = 0; r < RANK; r++) {
        if (valid)
            b[r] = *reinterpret_cast<const float4*>(B + (size_t)r * VOCAB + v);
        else
            b[r] = make_float4(0.f, 0.f, 0.f, 0.f);
    }

    // Cooperative load of this block's token-tile of low into shared
    __shared__ float slow[T_TILE * RANK];    // 2 KB
    const int tok0 = blockIdx.y * T_TILE;
    for (int i = threadIdx.x; i < T_TILE * RANK / 4; i += K2_THREADS) {
        reinterpret_cast<float4*>(slow)[i] =
            reinterpret_cast<const float4*>(g_low + (size_t)tok0 * RANK)[i];
    }
    __syncthreads();

    if (!valid) return;

    float* __restrict__ op = out + (size_t)tok0 * VOCAB + v;

#pragma unroll 4
    for (int tt = 0; tt < T_TILE; tt++) {
        const float* l = slow + tt * RANK;   // broadcast shared reads
        float4 o;
        o.x = l[0] * b[0].x; o.y = l[0] * b[0].y; o.z = l[0] * b[0].z; o.w = l[0] * b[0].w;
#pragma unroll
        for (int r = 1; r < RANK; r++) {
            o.x = fmaf(l[r], b[r].x, o.x);
            o.y = fmaf(l[r], b[r].y, o.y);
            o.z = fmaf(l[r], b[r].z, o.z);
            o.w = fmaf(l[r], b[r].w, o.w);
        }
        __stcs(reinterpret_cast<float4*>(op), o);   // streaming store, skip L2 retention
        op += VOCAB;
    }
}

// ---------------------------------------------------------------------------
// Launch
// ---------------------------------------------------------------------------
extern "C" void kernel_launch(void* const* d_in, const int* in_sizes, int n_in,
                              void* d_out, int out_size)
{
    const float* hidden = (const float*)d_in[0];   // [2,2048,1024]
    const float* A      = (const float*)d_in[1];   // [16,1024,8]
    const float* B      = (const float*)d_in[2];   // [8,32000]
    const float* alpha  = (const float*)d_in[3];   // scalar
    float* out          = (float*)d_out;           // [2,2048,32000]

    lowproj_kernel<<<NTOK / K1_TOKS, K1_TPB>>>(hidden, A, alpha);

    dim3 grid2((V4 + K2_THREADS - 1) / K2_THREADS,   // 32
               NTOK / T_TILE);                       // 64
    vocabproj_kernel<<<grid2, K2_THREADS>>>(B, out);
}

// round 5
// speedup vs baseline: 1.2946x; 1.2147x over previous
#include <cuda_runtime.h>
#include <cstdint>

// Problem constants
#define NBUCKETS 16
#define EMBD     1024
#define VOCAB    32000
#define SEQLEN   2048
#define RANK     8
#define BATCH    2
#define NTOK     (BATCH * SEQLEN)          // 4096 tokens
#define BUCKET_SHIFT 7                      // SEQLEN / NBUCKETS = 128 = 1<<7

// Scratch for the low-rank projection (alpha folded in): [NTOK][RANK]
__device__ float g_low[NTOK * RANK];

// ---------------------------------------------------------------------------
// Kernel 1 (v3): low[bt][r] = alpha * sum_e hidden[bt][e] * A[bucket(t)][e][r]
//
// 128 CTAs x 32 tokens (full-chip wave; 32 | 128 so tiles never cross a
// bucket). A-bucket loaded once per CTA into shared, transposed. Each warp
// handles 4 tokens simultaneously so every shared A-vector read is amortized
// over 4 tokens (LDS 512 -> 64 per thread vs R3). Warp-wide split-butterfly
// reduces all 32 accumulators (4 tok x 8 r) in 31 shuffles, then the warp
// stores one coalesced 128B line.
// ---------------------------------------------------------------------------
#define K1_TOKS 32
#define K1_TPB  256
#define TPW     4            // tokens per warp

__global__ __launch_bounds__(K1_TPB)
void lowproj_kernel(const float* __restrict__ hidden,
                    const float* __restrict__ A,
                    const float* __restrict__ alpha_p)
{
    __shared__ float sAT[RANK][EMBD];   // 32 KB, transposed A bucket

    const int tok0   = blockIdx.x * K1_TOKS;
    const int bucket = (tok0 & (SEQLEN - 1)) >> BUCKET_SHIFT;
    const float* __restrict__ Ab = A + (size_t)bucket * EMBD * RANK;

    // Cooperative load + transpose: 2048 float4, 8 per thread.
    for (int i = threadIdx.x; i < EMBD * RANK / 4; i += K1_TPB) {
        float4 v = reinterpret_cast<const float4*>(Ab)[i];
        const int e = i >> 1;
        const int q = (i & 1) * 4;
        sAT[q + 0][e] = v.x;
        sAT[q + 1][e] = v.y;
        sAT[q + 2][e] = v.z;
        sAT[q + 3][e] = v.w;
    }
    __syncthreads();

    const float alpha = alpha_p[0];
    const int wid  = threadIdx.x >> 5;
    const int lane = threadIdx.x & 31;
    const int wtok = tok0 + wid * TPW;           // first of this warp's 4 tokens
    const float* __restrict__ h0 = hidden + (size_t)wtok * EMBD;

    // acc value index i = g*8 + r  (g = token-in-warp, r = rank)
    float v[TPW * RANK];
#pragma unroll
    for (int i = 0; i < TPW * RANK; i++) v[i] = 0.0f;

    // lane covers e = lane*4 + k*128, k = 0..7
#pragma unroll
    for (int k = 0; k < EMBD / 128; k++) {
        const int e = lane * 4 + k * 128;
        float4 hv[TPW];
#pragma unroll
        for (int g = 0; g < TPW; g++)
            hv[g] = __ldcs(reinterpret_cast<const float4*>(h0 + (size_t)g * EMBD + e));
#pragma unroll
        for (int r = 0; r < RANK; r++) {
            const float4 av = *reinterpret_cast<const float4*>(&sAT[r][e]);
#pragma unroll
            for (int g = 0; g < TPW; g++) {
                v[g * RANK + r] = fmaf(hv[g].x, av.x,
                                  fmaf(hv[g].y, av.y,
                                  fmaf(hv[g].z, av.z,
                                  fmaf(hv[g].w, av.w, v[g * RANK + r]))));
            }
        }
    }

    // Split-butterfly reduce: 32 values across 32 lanes -> lane i holds the
    // lane-sum of value i. Value count halves each stage: 16+8+4+2+1 = 31 shfl.
#pragma unroll
    for (int m = 16; m >= 1; m >>= 1) {
        const bool hi = (lane & m) != 0;
        const int h = m;                 // current half-count == m
#pragma unroll
        for (int j = 0; j < 16; j++) {   // only j < h is live; guard below
            if (j < h) {
                float mine   = hi ? v[h + j] : v[j];
                float theirs = hi ? v[j]     : v[h + j];
                float other  = __shfl_xor_sync(0xFFFFFFFFu, theirs, m);
                v[j] = mine + other;
            }
        }
    }

    // lane l holds the sum for token g = l>>3, rank r = l&7.
    // 32 lanes store one contiguous 128B line: g_low[wtok*8 .. wtok*8+31]
    g_low[(size_t)wtok * RANK + lane] = v[0] * alpha;
}

// ---------------------------------------------------------------------------
// Kernel 2: out[bt][v] = sum_r low[bt][r] * B[r][v]
// (unchanged — measured ~6.07 TB/s store bandwidth, at the HBM/LTS cap)
// ---------------------------------------------------------------------------
#define T_TILE 64
#define K2_THREADS 256
#define V4 (VOCAB / 4)        // 8000 float4 per row

__global__ __launch_bounds__(K2_THREADS, 4)
void vocabproj_kernel(const float* __restrict__ B,
                      float* __restrict__ out)
{
    const int v4  = blockIdx.x * K2_THREADS + threadIdx.x;  // float4 column index
    const bool valid = (v4 < V4);
    const int v = v4 * 4;

    // Load B panel into registers: 8 rows x 4 cols
    float4 b[RANK];
#pragma unroll
    for (int r = 0; r < RANK; r++) {
        if (valid)
            b[r] = *reinterpret_cast<const float4*>(B + (size_t)r * VOCAB + v);
        else
            b[r] = make_float4(0.f, 0.f, 0.f, 0.f);
    }

    // Cooperative load of this block's token-tile of low into shared
    __shared__ float slow[T_TILE * RANK];    // 2 KB
    const int tok0 = blockIdx.y * T_TILE;
    for (int i = threadIdx.x; i < T_TILE * RANK / 4; i += K2_THREADS) {
        reinterpret_cast<float4*>(slow)[i] =
            reinterpret_cast<const float4*>(g_low + (size_t)tok0 * RANK)[i];
    }
    __syncthreads();

    if (!valid) return;

    float* __restrict__ op = out + (size_t)tok0 * VOCAB + v;

#pragma unroll 4
    for (int tt = 0; tt < T_TILE; tt++) {
        const float* l = slow + tt * RANK;   // broadcast shared reads
        float4 o;
        o.x = l[0] * b[0].x; o.y = l[0] * b[0].y; o.z = l[0] * b[0].z; o.w = l[0] * b[0].w;
#pragma unroll
        for (int r = 1; r < RANK; r++) {
            o.x = fmaf(l[r], b[r].x, o.x);
            o.y = fmaf(l[r], b[r].y, o.y);
            o.z = fmaf(l[r], b[r].z, o.z);
            o.w = fmaf(l[r], b[r].w, o.w);
        }
        __stcs(reinterpret_cast<float4*>(op), o);   // streaming store, skip L2 retention
        op += VOCAB;
    }
}

// ---------------------------------------------------------------------------
// Launch
// ---------------------------------------------------------------------------
extern "C" void kernel_launch(void* const* d_in, const int* in_sizes, int n_in,
                              void* d_out, int out_size)
{
    const float* hidden = (const float*)d_in[0];   // [2,2048,1024]
    const float* A      = (const float*)d_in[1];   // [16,1024,8]
    const float* B      = (const float*)d_in[2];   // [8,32000]
    const float* alpha  = (const float*)d_in[3];   // scalar
    float* out          = (float*)d_out;           // [2,2048,32000]

    lowproj_kernel<<<NTOK / K1_TOKS, K1_TPB>>>(hidden, A, alpha);

    dim3 grid2((V4 + K2_THREADS - 1) / K2_THREADS,   // 32
               NTOK / T_TILE);                       // 64
    vocabproj_kernel<<<grid2, K2_THREADS>>>(B, out);
}